// round 14
// baseline (speedup 1.0000x reference)
#include <cuda_runtime.h>
#include <cuda_fp16.h>
#include <cstdint>

#define EMB 128
#define NR 6
#define NS 7
#define NB 8
#define MAXE 100000
#define EPAD 100096            // multiple of 256
#define MAXL 500000
#define PITCH 136              // fp16 per smem row (272B, conflict-free ldmatrix)

// ---------------- device scratch ----------------
static __device__ float g_P[MAXE * 56];                  // [e][s*8+b]
static __device__ __half g_G[(size_t)EPAD * 1024];       // [d][j*128+k] fp16
static __device__ __half g_B2[128 * 1024];               // = fp16(W_bilin) flat: [i][j*128+k]
static __device__ __half g_Bw[128 * 128];                // [n=i][k] = W_m[k][i]
// dst-bucket CSR
static __device__ int g_cnt[MAXE];
static __device__ int g_off[MAXE];
static __device__ int g_cur[MAXE];
static __device__ int g_bsum[128];
static __device__ int g_order[MAXL];

// ---------------- helpers ----------------
__device__ __forceinline__ uint32_t smem_u32(const void* p) {
    uint32_t a;
    asm("{ .reg .u64 t; cvta.to.shared.u64 t, %1; cvt.u32.u64 %0, t; }" : "=r"(a) : "l"(p));
    return a;
}
__device__ __forceinline__ void ldsm4(uint32_t* r, uint32_t addr) {
    asm volatile("ldmatrix.sync.aligned.m8n8.x4.shared.b16 {%0,%1,%2,%3}, [%4];"
                 : "=r"(r[0]), "=r"(r[1]), "=r"(r[2]), "=r"(r[3]) : "r"(addr));
}
__device__ __forceinline__ void mma16816(float* c, const uint32_t* a, const uint32_t* b) {
    asm volatile(
        "mma.sync.aligned.m16n8k16.row.col.f32.f16.f16.f32 "
        "{%0,%1,%2,%3}, {%4,%5,%6,%7}, {%8,%9}, {%0,%1,%2,%3};"
        : "+f"(c[0]), "+f"(c[1]), "+f"(c[2]), "+f"(c[3])
        : "r"(a[0]), "r"(a[1]), "r"(a[2]), "r"(a[3]), "r"(b[0]), "r"(b[1]));
}

// ---------------- prep kernels ----------------
__global__ void prep_B2(const float* __restrict__ W_bilin) {
    int idx = blockIdx.x * blockDim.x + threadIdx.x;  // 128*1024
    if (idx < 128 * 1024) g_B2[idx] = __float2half_rn(W_bilin[idx]);
}
__global__ void prep_Bw(const float* __restrict__ W_m) {
    int idx = blockIdx.x * blockDim.x + threadIdx.x;  // 128*128
    if (idx < 128 * 128) {
        int n = idx >> 7, k = idx & 127;
        g_Bw[idx] = __float2half_rn(W_m[k * EMB + n]);
    }
}
__global__ void prep_P(const float* __restrict__ rbf,
                       const float* __restrict__ W_sbf, int E) {
    int idx = blockIdx.x * blockDim.x + threadIdx.x;  // E*8
    if (idx >= E * 8) return;
    int e = idx >> 3, b = idx & 7;
    float rb[NR];
#pragma unroll
    for (int r = 0; r < NR; ++r) rb[r] = rbf[e * NR + r];
#pragma unroll
    for (int s = 0; s < NS; ++s) {
        float acc = 0.f;
#pragma unroll
        for (int r = 0; r < NR; ++r) acc += rb[r] * W_sbf[(s * NR + r) * NB + b];
        g_P[e * 56 + s * 8 + b] = acc;
    }
}

// ---------------- dst-bucket CSR build ----------------
__global__ void zero_cnt(int E) {
    int i = blockIdx.x * blockDim.x + threadIdx.x;
    if (i < E) g_cnt[i] = 0;
}
__global__ void count_k(const int* __restrict__ lg_dst, int L) {
    int l = blockIdx.x * blockDim.x + threadIdx.x;
    if (l < L) atomicAdd(&g_cnt[lg_dst[l]], 1);
}
__global__ void scan1(int E) {
    __shared__ int s[1024];
    int t = threadIdx.x, i = blockIdx.x * 1024 + t;
    int v = (i < E) ? g_cnt[i] : 0;
    s[t] = v;
    __syncthreads();
    for (int d = 512; d > 0; d >>= 1) {
        if (t < d) s[t] += s[t + d];
        __syncthreads();
    }
    if (t == 0) g_bsum[blockIdx.x] = s[0];
}
__global__ void scan2(int nblk) {
    __shared__ int s[128];
    int t = threadIdx.x;
    int v = (t < nblk) ? g_bsum[t] : 0;
    s[t] = v;
    __syncthreads();
#pragma unroll
    for (int d = 1; d < 128; d <<= 1) {
        int x = (t >= d) ? s[t - d] : 0;
        __syncthreads();
        s[t] += x;
        __syncthreads();
    }
    if (t < nblk) g_bsum[t] = s[t] - v;
}
__global__ void scan3(int E) {
    __shared__ int s[1024];
    int t = threadIdx.x, i = blockIdx.x * 1024 + t;
    int v = (i < E) ? g_cnt[i] : 0;
    s[t] = v;
    __syncthreads();
    for (int d = 1; d < 1024; d <<= 1) {
        int x = (t >= d) ? s[t - d] : 0;
        __syncthreads();
        s[t] += x;
        __syncthreads();
    }
    if (i < E) {
        int off = g_bsum[blockIdx.x] + s[t] - v;
        g_off[i] = off;
        g_cur[i] = off;
    }
}
__global__ void scatter_k(const int* __restrict__ lg_dst, int L) {
    int l = blockIdx.x * blockDim.x + threadIdx.x;
    if (l < L) {
        int pos = atomicAdd(&g_cur[lg_dst[l]], 1);
        g_order[pos] = l;
    }
}

// ---------------- w GEMM: CTA 256Mx128N, K=128, 8 warps, warp 64x64 ----------------
__global__ __launch_bounds__(256, 1) void w_gemm(
    const float* __restrict__ m, const float* __restrict__ rbf,
    const float* __restrict__ W_rbf, const float* __restrict__ b_m,
    float* __restrict__ w_out, int E) {
    extern __shared__ __half sm[];
    __half* Ah = sm;                 // 256 x PITCH
    __half* Bh = sm + 256 * PITCH;   // 128 x PITCH

    const int tid = threadIdx.x;
    const int lane = tid & 31, wid = tid >> 5;
    const int wm = wid >> 1, wn = wid & 1;
    const int e0 = blockIdx.x * 256;

    // stage A: 256 rows x 32 float4, convert to fp16
    {
        const float4* sA = (const float4*)m + (size_t)e0 * 32;
#pragma unroll
        for (int it = 0; it < 32; ++it) {
            int idx = it * 256 + tid;      // 0..8191
            int row = idx >> 5, v = idx & 31;
            float4 f = (e0 + row < E) ? sA[(size_t)row * 32 + v]
                                      : make_float4(0.f, 0.f, 0.f, 0.f);
            __half2 h01 = __floats2half2_rn(f.x, f.y);
            __half2 h23 = __floats2half2_rn(f.z, f.w);
            uint2 pk;
            pk.x = *(uint32_t*)&h01;
            pk.y = *(uint32_t*)&h23;
            *(uint2*)(Ah + row * PITCH + v * 4) = pk;
        }
        // stage B: 128 rows x 16 uint4 = 2048  (FIXED: was 8 uint4/row)
        const uint4* sB = (const uint4*)g_Bw;
#pragma unroll
        for (int it = 0; it < 8; ++it) {
            int idx = it * 256 + tid;      // 0..2047
            int row = idx >> 4, v = idx & 15;
            *(uint4*)(Bh + row * PITCH + v * 8) = sB[(size_t)row * 16 + v];
        }
    }
    __syncthreads();

    const int a_row = wm * 64 + (lane & 15);
    const int a_k = (lane >> 4) * 8;
    uint32_t ah_b = smem_u32(Ah) + (a_row * PITCH + a_k) * 2;
    const int b_row = wn * 64 + ((lane >> 4) & 1) * 8 + (lane & 7);
    const int b_k = ((lane >> 3) & 1) * 8;
    uint32_t bh_b = smem_u32(Bh) + (b_row * PITCH + b_k) * 2;

    float c[4][8][4];
#pragma unroll
    for (int mi = 0; mi < 4; ++mi)
#pragma unroll
        for (int ni = 0; ni < 8; ++ni)
#pragma unroll
            for (int q = 0; q < 4; ++q) c[mi][ni][q] = 0.f;

    for (int kt = 0; kt < 8; ++kt) {
        const uint32_t ko = kt * 32;
        uint32_t ah[4][4], bh[4][4];
#pragma unroll
        for (int mi = 0; mi < 4; ++mi) ldsm4(ah[mi], ah_b + mi * 16 * PITCH * 2 + ko);
#pragma unroll
        for (int g = 0; g < 4; ++g) ldsm4(bh[g], bh_b + g * 16 * PITCH * 2 + ko);
#pragma unroll
        for (int mi = 0; mi < 4; ++mi)
#pragma unroll
            for (int ni = 0; ni < 8; ++ni)
                mma16816(c[mi][ni], ah[mi], &bh[ni >> 1][(ni & 1) * 2]);
    }

    const int r_lo = lane >> 2;
    const int c_lo = (lane & 3) * 2;
#pragma unroll
    for (int mi = 0; mi < 4; ++mi) {
        int r0 = e0 + wm * 64 + mi * 16 + r_lo;
#pragma unroll
        for (int half = 0; half < 2; ++half) {
            int e = r0 + half * 8;
            if (e >= E) continue;
            float rb[NR];
#pragma unroll
            for (int q = 0; q < NR; ++q) rb[q] = rbf[e * NR + q];
#pragma unroll
            for (int ni = 0; ni < 8; ++ni) {
#pragma unroll
                for (int p = 0; p < 2; ++p) {
                    int i = wn * 64 + ni * 8 + c_lo + p;
                    float h = c[mi][ni][half * 2 + p] + b_m[i];
                    float sg = h / (1.f + __expf(-h));
                    float rw = 0.f;
#pragma unroll
                    for (int q = 0; q < NR; ++q) rw += rb[q] * W_rbf[q * EMB + i];
                    w_out[(size_t)e * EMB + i] = rw * sg;
                }
            }
        }
    }
}

// ---------------- G build: warp per DST edge ----------------
// G[d,j,k] = sum_{l in bucket(d)} sbf[l,j] * m[src_l,k]; m gathered fp32 (L2-resident).
__global__ __launch_bounds__(256) void g_build(
    const float* __restrict__ o, const float* __restrict__ m,
    const int* __restrict__ lg_src, int E) {
    const int warp = (blockIdx.x * blockDim.x + threadIdx.x) >> 5;
    const int lane = threadIdx.x & 31;
    if (warp >= E) return;
    const int d = warp;
    const int n = g_cnt[d];
    const int base = g_off[d];

    float acc[8][4];
#pragma unroll
    for (int j = 0; j < 8; ++j)
#pragma unroll
        for (int q = 0; q < 4; ++q) acc[j][q] = 0.f;

    float x2o = 0.f, y2o = 0.f, z2o = 0.f;
    if (lane < 8 && n > 0) {
        x2o = o[d * 3];
        y2o = o[d * 3 + 1];
        z2o = o[d * 3 + 2];
    }

    for (int t = 0; t < n; ++t) {
        int l = g_order[base + t];
        int src = lg_src[l];
        float sbf = 0.f;
        if (lane < 8) {
            float x1 = o[src * 3], y1 = o[src * 3 + 1], z1 = o[src * 3 + 2];
            float dot = x1 * x2o + y1 * y2o + z1 * z2o;
            float cx = y1 * z2o - z1 * y2o;
            float cy = z1 * x2o - x1 * z2o;
            float cz = x1 * y2o - y1 * x2o;
            float cr2 = cx * cx + cy * cy + cz * cz;
            float ct = dot / sqrtf(dot * dot + cr2);
            ct = fminf(1.f, fmaxf(-1.f, ct));
            const float* Pp = g_P + (size_t)src * 56 + lane;
            float c0 = 1.f, c1 = ct;
            sbf = Pp[0] + ct * Pp[8];
#pragma unroll
            for (int s = 2; s < NS; ++s) {
                float c2 = 2.f * ct * c1 - c0;
                sbf += c2 * Pp[s * 8];
                c0 = c1;
                c1 = c2;
            }
        }
        float sb[8];
#pragma unroll
        for (int j = 0; j < 8; ++j) sb[j] = __shfl_sync(0xffffffffu, sbf, j);

        float4 mv = ((const float4*)m)[(size_t)src * 32 + lane];
#pragma unroll
        for (int j = 0; j < 8; ++j) {
            acc[j][0] += sb[j] * mv.x;
            acc[j][1] += sb[j] * mv.y;
            acc[j][2] += sb[j] * mv.z;
            acc[j][3] += sb[j] * mv.w;
        }
    }

    __half* gg = g_G + (size_t)d * 1024;
#pragma unroll
    for (int j = 0; j < 8; ++j) {
        __half2 h01 = __floats2half2_rn(acc[j][0], acc[j][1]);
        __half2 h23 = __floats2half2_rn(acc[j][2], acc[j][3]);
        uint2 pk;
        pk.x = *(uint32_t*)&h01;
        pk.y = *(uint32_t*)&h23;
        *(uint2*)&gg[j * 128 + lane * 4] = pk;
    }
}

// ---------------- G GEMM: m_update = G @ W_bilin^T ----------------
// CTA 256(d) x 128(i), K=1024 in 8 staged chunks. 8 warps, warp 64x64.
__global__ __launch_bounds__(256, 1) void g_gemm(float* __restrict__ m_upd, int E) {
    extern __shared__ __half sm[];
    __half* Ah = sm;                 // 256 x PITCH
    __half* Bh = sm + 256 * PITCH;   // 128 x PITCH

    const int tid = threadIdx.x;
    const int lane = tid & 31, wid = tid >> 5;
    const int wm = wid >> 1, wn = wid & 1;
    const int e0 = blockIdx.x * 256;

    const int a_row = wm * 64 + (lane & 15);
    const int a_k = (lane >> 4) * 8;
    uint32_t ah_b = smem_u32(Ah) + (a_row * PITCH + a_k) * 2;
    const int b_row = wn * 64 + ((lane >> 4) & 1) * 8 + (lane & 7);
    const int b_k = ((lane >> 3) & 1) * 8;
    uint32_t bh_b = smem_u32(Bh) + (b_row * PITCH + b_k) * 2;

    float c[4][8][4];
#pragma unroll
    for (int mi = 0; mi < 4; ++mi)
#pragma unroll
        for (int ni = 0; ni < 8; ++ni)
#pragma unroll
            for (int q = 0; q < 4; ++q) c[mi][ni][q] = 0.f;

    for (int kc = 0; kc < 8; ++kc) {
        const uint4* sA = (const uint4*)(g_G + (size_t)e0 * 1024 + kc * 128);
        const uint4* sB = (const uint4*)(g_B2 + (size_t)kc * 128);
#pragma unroll
        for (int it = 0; it < 16; ++it) {
            int idx = it * 256 + tid;      // 0..4095
            int row = idx >> 4, v = idx & 15;
            *(uint4*)(Ah + row * PITCH + v * 8) = sA[(size_t)row * 128 + v];
        }
#pragma unroll
        for (int it = 0; it < 8; ++it) {
            int idx = it * 256 + tid;      // 0..2047
            int row = idx >> 4, v = idx & 15;
            *(uint4*)(Bh + row * PITCH + v * 8) = sB[(size_t)row * 128 + v];
        }
        __syncthreads();

        for (int kt = 0; kt < 8; ++kt) {
            const uint32_t ko = kt * 32;
            uint32_t ah[4][4], bh[4][4];
#pragma unroll
            for (int mi = 0; mi < 4; ++mi) ldsm4(ah[mi], ah_b + mi * 16 * PITCH * 2 + ko);
#pragma unroll
            for (int g = 0; g < 4; ++g) ldsm4(bh[g], bh_b + g * 16 * PITCH * 2 + ko);
#pragma unroll
            for (int mi = 0; mi < 4; ++mi)
#pragma unroll
                for (int ni = 0; ni < 8; ++ni)
                    mma16816(c[mi][ni], ah[mi], &bh[ni >> 1][(ni & 1) * 2]);
        }
        __syncthreads();
    }

    const int r_lo = lane >> 2;
    const int c_lo = (lane & 3) * 2;
#pragma unroll
    for (int mi = 0; mi < 4; ++mi) {
        int r0 = e0 + wm * 64 + mi * 16 + r_lo;
#pragma unroll
        for (int ni = 0; ni < 8; ++ni) {
            int col = wn * 64 + ni * 8 + c_lo;
            if (r0 < E)
                *(float2*)&m_upd[(size_t)r0 * 128 + col] =
                    make_float2(c[mi][ni][0], c[mi][ni][1]);
            if (r0 + 8 < E)
                *(float2*)&m_upd[(size_t)(r0 + 8) * 128 + col] =
                    make_float2(c[mi][ni][2], c[mi][ni][3]);
        }
    }
}

// ---------------- launch ----------------
extern "C" void kernel_launch(void* const* d_in, const int* in_sizes, int n_in,
                              void* d_out, int out_size) {
    const float* rbf     = (const float*)d_in[0];
    const float* m       = (const float*)d_in[1];
    const float* o       = (const float*)d_in[2];
    const int*   lg_src  = (const int*)d_in[3];
    const int*   lg_dst  = (const int*)d_in[4];
    const float* W_rbf   = (const float*)d_in[5];
    const float* W_m     = (const float*)d_in[6];
    const float* b_m     = (const float*)d_in[7];
    const float* W_sbf   = (const float*)d_in[8];
    const float* W_bilin = (const float*)d_in[9];

    const int E = in_sizes[1] / EMB;   // 100000
    const int L = in_sizes[3];         // 500000
    const int nblk = (E + 1023) / 1024;

    float* w_out = (float*)d_out;                    // [E,128]
    float* m_upd = w_out + (size_t)E * EMB;          // [E,128]

    const int dynsmem = (256 + 128) * PITCH * 2;  // 104448 bytes
    cudaFuncSetAttribute(w_gemm, cudaFuncAttributeMaxDynamicSharedMemorySize, dynsmem);
    cudaFuncSetAttribute(g_gemm, cudaFuncAttributeMaxDynamicSharedMemorySize, dynsmem);

    prep_B2<<<(128 * 1024 + 255) / 256, 256>>>(W_bilin);             // 1
    prep_Bw<<<(128 * 128 + 255) / 256, 256>>>(W_m);                  // 2
    prep_P<<<(E * 8 + 255) / 256, 256>>>(rbf, W_sbf, E);             // 3

    w_gemm<<<(E + 255) / 256, 256, dynsmem>>>(m, rbf, W_rbf, b_m, w_out, E);  // 4 <- profiled

    zero_cnt<<<(E + 255) / 256, 256>>>(E);                           // 5
    count_k<<<(L + 255) / 256, 256>>>(lg_dst, L);                    // 6
    scan1<<<nblk, 1024>>>(E);                                        // 7
    scan2<<<1, 128>>>(nblk);                                         // 8
    scan3<<<nblk, 1024>>>(E);                                        // 9
    scatter_k<<<(L + 255) / 256, 256>>>(lg_dst, L);                  // 10

    g_build<<<(E * 32 + 255) / 256, 256>>>(o, m, lg_src, E);         // 11
    g_gemm<<<(E + 255) / 256, 256, dynsmem>>>(m_upd, E);             // 12
}

// round 15
// speedup vs baseline: 1.1287x; 1.1287x over previous
#include <cuda_runtime.h>
#include <cuda_fp16.h>
#include <cstdint>

#define EMB 128
#define NR 6
#define NS 7
#define NB 8
#define MAXE 100000
#define EPAD 100096            // multiple of 256
#define MAXL 500000
#define PITCH 136              // fp16 per smem row (272B, conflict-free ldmatrix)

// ---------------- device scratch ----------------
static __device__ float g_P[MAXE * 56];                  // [e][s*8+b]
static __device__ __half g_G[(size_t)EPAD * 1024];       // [d][j*128+k] fp16
static __device__ __half g_B2[128 * 1024];               // fp16(W_bilin) flat [i][j*128+k]
static __device__ __half g_Bw[128 * 128];                // [n=i][k] = W_m[k][i]
// dst-bucket CSR
static __device__ int g_cnt[MAXE];
static __device__ int g_off[MAXE];
static __device__ int g_cur[MAXE];
static __device__ int g_bsum[128];
static __device__ int g_order[MAXL];

// ---------------- helpers ----------------
__device__ __forceinline__ uint32_t smem_u32(const void* p) {
    uint32_t a;
    asm("{ .reg .u64 t; cvta.to.shared.u64 t, %1; cvt.u32.u64 %0, t; }" : "=r"(a) : "l"(p));
    return a;
}
__device__ __forceinline__ void ldsm4(uint32_t* r, uint32_t addr) {
    asm volatile("ldmatrix.sync.aligned.m8n8.x4.shared.b16 {%0,%1,%2,%3}, [%4];"
                 : "=r"(r[0]), "=r"(r[1]), "=r"(r[2]), "=r"(r[3]) : "r"(addr));
}
__device__ __forceinline__ void mma16816(float* c, const uint32_t* a, const uint32_t* b) {
    asm volatile(
        "mma.sync.aligned.m16n8k16.row.col.f32.f16.f16.f32 "
        "{%0,%1,%2,%3}, {%4,%5,%6,%7}, {%8,%9}, {%0,%1,%2,%3};"
        : "+f"(c[0]), "+f"(c[1]), "+f"(c[2]), "+f"(c[3])
        : "r"(a[0]), "r"(a[1]), "r"(a[2]), "r"(a[3]), "r"(b[0]), "r"(b[1]));
}

// ---------------- merged prep kernel ----------------
// idx ranges: [0, 131072) -> B2; [131072, 147456) -> Bw; [147456, 147456+E*8) -> P
__global__ void prep_all(const float* __restrict__ W_bilin,
                         const float* __restrict__ W_m,
                         const float* __restrict__ rbf,
                         const float* __restrict__ W_sbf, int E) {
    int idx = blockIdx.x * blockDim.x + threadIdx.x;
    if (idx < 131072) {
        g_B2[idx] = __float2half_rn(W_bilin[idx]);
    } else if (idx < 147456) {
        int q = idx - 131072;
        int n = q >> 7, k = q & 127;
        g_Bw[q] = __float2half_rn(W_m[k * EMB + n]);
    } else {
        int q = idx - 147456;
        if (q >= E * 8) return;
        int e = q >> 3, b = q & 7;
        float rb[NR];
#pragma unroll
        for (int r = 0; r < NR; ++r) rb[r] = rbf[e * NR + r];
#pragma unroll
        for (int s = 0; s < NS; ++s) {
            float acc = 0.f;
#pragma unroll
            for (int r = 0; r < NR; ++r) acc += rb[r] * W_sbf[(s * NR + r) * NB + b];
            g_P[e * 56 + s * 8 + b] = acc;
        }
    }
}

// ---------------- dst-bucket CSR build ----------------
__global__ void zero_cnt(int E) {
    int i = blockIdx.x * blockDim.x + threadIdx.x;
    if (i < E) g_cnt[i] = 0;
}
__global__ void count_k(const int* __restrict__ lg_dst, int L) {
    int l = blockIdx.x * blockDim.x + threadIdx.x;
    if (l < L) atomicAdd(&g_cnt[lg_dst[l]], 1);
}
__global__ void scan1(int E) {
    __shared__ int s[1024];
    int t = threadIdx.x, i = blockIdx.x * 1024 + t;
    int v = (i < E) ? g_cnt[i] : 0;
    s[t] = v;
    __syncthreads();
    for (int d = 512; d > 0; d >>= 1) {
        if (t < d) s[t] += s[t + d];
        __syncthreads();
    }
    if (t == 0) g_bsum[blockIdx.x] = s[0];
}
__global__ void scan2(int nblk) {
    __shared__ int s[128];
    int t = threadIdx.x;
    int v = (t < nblk) ? g_bsum[t] : 0;
    s[t] = v;
    __syncthreads();
#pragma unroll
    for (int d = 1; d < 128; d <<= 1) {
        int x = (t >= d) ? s[t - d] : 0;
        __syncthreads();
        s[t] += x;
        __syncthreads();
    }
    if (t < nblk) g_bsum[t] = s[t] - v;
}
__global__ void scan3(int E) {
    __shared__ int s[1024];
    int t = threadIdx.x, i = blockIdx.x * 1024 + t;
    int v = (i < E) ? g_cnt[i] : 0;
    s[t] = v;
    __syncthreads();
    for (int d = 1; d < 1024; d <<= 1) {
        int x = (t >= d) ? s[t - d] : 0;
        __syncthreads();
        s[t] += x;
        __syncthreads();
    }
    if (i < E) {
        int off = g_bsum[blockIdx.x] + s[t] - v;
        g_off[i] = off;
        g_cur[i] = off;
    }
}
__global__ void scatter_k(const int* __restrict__ lg_dst, int L) {
    int l = blockIdx.x * blockDim.x + threadIdx.x;
    if (l < L) {
        int pos = atomicAdd(&g_cur[lg_dst[l]], 1);
        g_order[pos] = l;
    }
}

// ---------------- w GEMM: CTA 256Mx128N, K=128; smem-resident epilogue ----------------
// smem layout (bytes): Ah[0,69632) Bh[69632,104448) sW[104448,107520)
//                      sbm[107520,108032) srbf[108032,114176)
__global__ __launch_bounds__(256, 1) void w_gemm(
    const float* __restrict__ m, const float* __restrict__ rbf,
    const float* __restrict__ W_rbf, const float* __restrict__ b_m,
    float* __restrict__ w_out, int E) {
    extern __shared__ char smraw[];
    __half* Ah = (__half*)smraw;
    __half* Bh = (__half*)(smraw + 69632);
    float* sW = (float*)(smraw + 104448);    // [6][128]
    float* sbm = (float*)(smraw + 107520);   // [128]
    float* srbf = (float*)(smraw + 108032);  // [256][6]

    const int tid = threadIdx.x;
    const int lane = tid & 31, wid = tid >> 5;
    const int wm = wid >> 1, wn = wid & 1;
    const int e0 = blockIdx.x * 256;

    // stage A (fp32 m -> fp16), B, and epilogue tables
    {
        const float4* sA = (const float4*)m + (size_t)e0 * 32;
#pragma unroll
        for (int it = 0; it < 32; ++it) {
            int idx = it * 256 + tid;      // 0..8191
            int row = idx >> 5, v = idx & 31;
            float4 f = (e0 + row < E) ? sA[(size_t)row * 32 + v]
                                      : make_float4(0.f, 0.f, 0.f, 0.f);
            __half2 h01 = __floats2half2_rn(f.x, f.y);
            __half2 h23 = __floats2half2_rn(f.z, f.w);
            uint2 pk;
            pk.x = *(uint32_t*)&h01;
            pk.y = *(uint32_t*)&h23;
            *(uint2*)(Ah + row * PITCH + v * 4) = pk;
        }
        const uint4* sB = (const uint4*)g_Bw;
#pragma unroll
        for (int it = 0; it < 8; ++it) {
            int idx = it * 256 + tid;      // 0..2047
            int row = idx >> 4, v = idx & 15;
            *(uint4*)(Bh + row * PITCH + v * 8) = sB[(size_t)row * 16 + v];
        }
#pragma unroll
        for (int it = 0; it < 3; ++it) {
            int idx = it * 256 + tid;
            if (idx < 768) sW[idx] = W_rbf[idx];  // [q][i] row-major, matches W_rbf
        }
        if (tid < 128) sbm[tid] = b_m[tid];
#pragma unroll
        for (int it = 0; it < 6; ++it) {
            int idx = it * 256 + tid;      // 0..1535
            int row = idx / 6;
            srbf[idx] = (e0 + row < E) ? rbf[(size_t)(e0 + row) * NR + (idx - row * 6)] : 0.f;
        }
    }
    __syncthreads();

    const int a_row = wm * 64 + (lane & 15);
    const int a_k = (lane >> 4) * 8;
    uint32_t ah_b = smem_u32(Ah) + (a_row * PITCH + a_k) * 2;
    const int b_row = wn * 64 + ((lane >> 4) & 1) * 8 + (lane & 7);
    const int b_k = ((lane >> 3) & 1) * 8;
    uint32_t bh_b = smem_u32(Bh) + (b_row * PITCH + b_k) * 2;

    float c[4][8][4];
#pragma unroll
    for (int mi = 0; mi < 4; ++mi)
#pragma unroll
        for (int ni = 0; ni < 8; ++ni)
#pragma unroll
            for (int q = 0; q < 4; ++q) c[mi][ni][q] = 0.f;

    for (int kt = 0; kt < 8; ++kt) {
        const uint32_t ko = kt * 32;
        uint32_t ah[4][4], bh[4][4];
#pragma unroll
        for (int mi = 0; mi < 4; ++mi) ldsm4(ah[mi], ah_b + mi * 16 * PITCH * 2 + ko);
#pragma unroll
        for (int g = 0; g < 4; ++g) ldsm4(bh[g], bh_b + g * 16 * PITCH * 2 + ko);
#pragma unroll
        for (int mi = 0; mi < 4; ++mi)
#pragma unroll
            for (int ni = 0; ni < 8; ++ni)
                mma16816(c[mi][ni], ah[mi], &bh[ni >> 1][(ni & 1) * 2]);
    }

    const int r_lo = lane >> 2;
    const int c_lo = (lane & 3) * 2;
#pragma unroll
    for (int mi = 0; mi < 4; ++mi) {
#pragma unroll
        for (int half = 0; half < 2; ++half) {
            int rloc = wm * 64 + mi * 16 + r_lo + half * 8;
            int e = e0 + rloc;
            if (e >= E) continue;
            float rb[NR];
#pragma unroll
            for (int q = 0; q < NR; ++q) rb[q] = srbf[rloc * 6 + q];
#pragma unroll
            for (int ni = 0; ni < 8; ++ni) {
#pragma unroll
                for (int p = 0; p < 2; ++p) {
                    int i = wn * 64 + ni * 8 + c_lo + p;
                    float h = c[mi][ni][half * 2 + p] + sbm[i];
                    float sg = h / (1.f + __expf(-h));
                    float rw = 0.f;
#pragma unroll
                    for (int q = 0; q < NR; ++q) rw += rb[q] * sW[q * 128 + i];
                    w_out[(size_t)e * EMB + i] = rw * sg;
                }
            }
        }
    }
}

// ---------------- G build: warp per DST edge ----------------
__global__ __launch_bounds__(256) void g_build(
    const float* __restrict__ o, const float* __restrict__ m,
    const int* __restrict__ lg_src, int E) {
    const int warp = (blockIdx.x * blockDim.x + threadIdx.x) >> 5;
    const int lane = threadIdx.x & 31;
    if (warp >= E) return;
    const int d = warp;
    const int n = g_cnt[d];
    const int base = g_off[d];

    float acc[8][4];
#pragma unroll
    for (int j = 0; j < 8; ++j)
#pragma unroll
        for (int q = 0; q < 4; ++q) acc[j][q] = 0.f;

    float x2o = 0.f, y2o = 0.f, z2o = 0.f;
    if (lane < 8 && n > 0) {
        x2o = o[d * 3];
        y2o = o[d * 3 + 1];
        z2o = o[d * 3 + 2];
    }

    for (int t = 0; t < n; ++t) {
        int l = g_order[base + t];
        int src = lg_src[l];
        float sbf = 0.f;
        if (lane < 8) {
            float x1 = o[src * 3], y1 = o[src * 3 + 1], z1 = o[src * 3 + 2];
            float dot = x1 * x2o + y1 * y2o + z1 * z2o;
            float cx = y1 * z2o - z1 * y2o;
            float cy = z1 * x2o - x1 * z2o;
            float cz = x1 * y2o - y1 * x2o;
            float cr2 = cx * cx + cy * cy + cz * cz;
            float ct = dot / sqrtf(dot * dot + cr2);
            ct = fminf(1.f, fmaxf(-1.f, ct));
            const float* Pp = g_P + (size_t)src * 56 + lane;
            float c0 = 1.f, c1 = ct;
            sbf = Pp[0] + ct * Pp[8];
#pragma unroll
            for (int s = 2; s < NS; ++s) {
                float c2 = 2.f * ct * c1 - c0;
                sbf += c2 * Pp[s * 8];
                c0 = c1;
                c1 = c2;
            }
        }
        float sb[8];
#pragma unroll
        for (int j = 0; j < 8; ++j) sb[j] = __shfl_sync(0xffffffffu, sbf, j);

        float4 mv = ((const float4*)m)[(size_t)src * 32 + lane];
#pragma unroll
        for (int j = 0; j < 8; ++j) {
            acc[j][0] += sb[j] * mv.x;
            acc[j][1] += sb[j] * mv.y;
            acc[j][2] += sb[j] * mv.z;
            acc[j][3] += sb[j] * mv.w;
        }
    }

    __half* gg = g_G + (size_t)d * 1024;
#pragma unroll
    for (int j = 0; j < 8; ++j) {
        __half2 h01 = __floats2half2_rn(acc[j][0], acc[j][1]);
        __half2 h23 = __floats2half2_rn(acc[j][2], acc[j][3]);
        uint2 pk;
        pk.x = *(uint32_t*)&h01;
        pk.y = *(uint32_t*)&h23;
        *(uint2*)&gg[j * 128 + lane * 4] = pk;
    }
}

// ---------------- G GEMM: m_update = G @ W_bilin^T ----------------
// CTA 128(d) x 128(i), K=1024 in 8 chunks. 8 warps (2m x 4n), warp 64x32.
// 2 CTAs/SM -> cross-CTA overlap of staging and mma.
__global__ __launch_bounds__(256, 2) void g_gemm(float* __restrict__ m_upd, int E) {
    extern __shared__ __half sm[];
    __half* Ah = sm;                 // 128 x PITCH
    __half* Bh = sm + 128 * PITCH;   // 128 x PITCH

    const int tid = threadIdx.x;
    const int lane = tid & 31, wid = tid >> 5;
    const int wm = wid >> 2, wn = wid & 3;
    const int e0 = blockIdx.x * 128;

    const int a_row = wm * 64 + (lane & 15);
    const int a_k = (lane >> 4) * 8;
    uint32_t ah_b = smem_u32(Ah) + (a_row * PITCH + a_k) * 2;
    const int b_row = wn * 32 + ((lane >> 4) & 1) * 8 + (lane & 7);
    const int b_k = ((lane >> 3) & 1) * 8;
    uint32_t bh_b = smem_u32(Bh) + (b_row * PITCH + b_k) * 2;

    float c[4][4][4];
#pragma unroll
    for (int mi = 0; mi < 4; ++mi)
#pragma unroll
        for (int ni = 0; ni < 4; ++ni)
#pragma unroll
            for (int q = 0; q < 4; ++q) c[mi][ni][q] = 0.f;

    for (int kc = 0; kc < 8; ++kc) {
        const uint4* sA = (const uint4*)(g_G + (size_t)e0 * 1024 + kc * 128);
        const uint4* sB = (const uint4*)(g_B2 + (size_t)kc * 128);
#pragma unroll
        for (int it = 0; it < 8; ++it) {
            int idx = it * 256 + tid;      // 0..2047
            int row = idx >> 4, v = idx & 15;
            *(uint4*)(Ah + row * PITCH + v * 8) = sA[(size_t)row * 128 + v];
        }
#pragma unroll
        for (int it = 0; it < 8; ++it) {
            int idx = it * 256 + tid;      // 0..2047
            int row = idx >> 4, v = idx & 15;
            *(uint4*)(Bh + row * PITCH + v * 8) = sB[(size_t)row * 128 + v];
        }
        __syncthreads();

        for (int kt = 0; kt < 8; ++kt) {
            const uint32_t ko = kt * 32;
            uint32_t ah[4][4], bh[2][4];
#pragma unroll
            for (int mi = 0; mi < 4; ++mi) ldsm4(ah[mi], ah_b + mi * 16 * PITCH * 2 + ko);
#pragma unroll
            for (int g = 0; g < 2; ++g) ldsm4(bh[g], bh_b + g * 16 * PITCH * 2 + ko);
#pragma unroll
            for (int mi = 0; mi < 4; ++mi)
#pragma unroll
                for (int ni = 0; ni < 4; ++ni)
                    mma16816(c[mi][ni], ah[mi], &bh[ni >> 1][(ni & 1) * 2]);
        }
        __syncthreads();
    }

    const int r_lo = lane >> 2;
    const int c_lo = (lane & 3) * 2;
#pragma unroll
    for (int mi = 0; mi < 4; ++mi) {
        int r0 = e0 + wm * 64 + mi * 16 + r_lo;
#pragma unroll
        for (int ni = 0; ni < 4; ++ni) {
            int col = wn * 32 + ni * 8 + c_lo;
            if (r0 < E)
                *(float2*)&m_upd[(size_t)r0 * 128 + col] =
                    make_float2(c[mi][ni][0], c[mi][ni][1]);
            if (r0 + 8 < E)
                *(float2*)&m_upd[(size_t)(r0 + 8) * 128 + col] =
                    make_float2(c[mi][ni][2], c[mi][ni][3]);
        }
    }
}

// ---------------- launch ----------------
extern "C" void kernel_launch(void* const* d_in, const int* in_sizes, int n_in,
                              void* d_out, int out_size) {
    const float* rbf     = (const float*)d_in[0];
    const float* m       = (const float*)d_in[1];
    const float* o       = (const float*)d_in[2];
    const int*   lg_src  = (const int*)d_in[3];
    const int*   lg_dst  = (const int*)d_in[4];
    const float* W_rbf   = (const float*)d_in[5];
    const float* W_m     = (const float*)d_in[6];
    const float* b_m     = (const float*)d_in[7];
    const float* W_sbf   = (const float*)d_in[8];
    const float* W_bilin = (const float*)d_in[9];

    const int E = in_sizes[1] / EMB;   // 100000
    const int L = in_sizes[3];         // 500000
    const int nblk = (E + 1023) / 1024;

    float* w_out = (float*)d_out;                    // [E,128]
    float* m_upd = w_out + (size_t)E * EMB;          // [E,128]

    const int w_smem = 114176;
    const int g_smem = 2 * 128 * PITCH * 2;  // 69632
    cudaFuncSetAttribute(w_gemm, cudaFuncAttributeMaxDynamicSharedMemorySize, w_smem);
    cudaFuncSetAttribute(g_gemm, cudaFuncAttributeMaxDynamicSharedMemorySize, g_smem);

    int prep_n = 147456 + E * 8;
    prep_all<<<(prep_n + 255) / 256, 256>>>(W_bilin, W_m, rbf, W_sbf, E);  // 1
    zero_cnt<<<(E + 255) / 256, 256>>>(E);                                  // 2
    count_k<<<(L + 255) / 256, 256>>>(lg_dst, L);                           // 3

    w_gemm<<<(E + 255) / 256, 256, w_smem>>>(m, rbf, W_rbf, b_m, w_out, E); // 4 <- profiled

    scan1<<<nblk, 1024>>>(E);                                               // 5
    scan2<<<1, 128>>>(nblk);                                                // 6
    scan3<<<nblk, 1024>>>(E);                                               // 7
    scatter_k<<<(L + 255) / 256, 256>>>(lg_dst, L);                         // 8

    g_build<<<(E * 32 + 255) / 256, 256>>>(o, m, lg_src, E);                // 9
    g_gemm<<<(E + 127) / 128, 256, g_smem>>>(m_upd, E);                     // 10
}